// round 17
// baseline (speedup 1.0000x reference)
#include <cuda_runtime.h>
#include <cstdint>

#define SZ 512
#define SLAB 128
#define NPLANES 256

// dynamic smem layout (bytes)
#define OFF_ROWP 0                     // float[4][128][33] row partials
#define OFF_COLP 67584                 // float[8][512] col partials (8 rowgroups)
#define OFF_PKM  83968                 // float[128]
#define OFF_PKA  84480
#define OFF_SNM  84992
#define OFF_SNA  85504
#define OFF_DAE  86016
#define OFF_BAND 86528                 // float[4][128]
#define OFF_CUTM 88576
#define OFF_CUTA 89088
#define SMEM_TOTAL 89600

// cross-block scratch (allocation-free: __device__ globals)
__device__ float g_colsum[NPLANES][4][SZ];
__device__ float g_snapM[NPLANES][SZ];
__device__ float g_snapA[NPLANES][SZ];
__device__ float g_RT[NPLANES][SZ];
__device__ float g_PM[NPLANES][SZ];
__device__ float g_PA[NPLANES][SZ];
__device__ float g_DA[NPLANES][SZ];
__device__ unsigned int g_cnt[NPLANES];   // zero-init; self-reset each launch

__device__ __forceinline__ uint64_t pack2(float lo, float hi) {
    uint64_t d; asm("mov.b64 %0, {%1, %2};" : "=l"(d) : "f"(lo), "f"(hi)); return d;
}
__device__ __forceinline__ void unpack2(uint64_t d, float& lo, float& hi) {
    asm("mov.b64 {%0, %1}, %2;" : "=f"(lo), "=f"(hi) : "l"(d));
}
__device__ __forceinline__ uint64_t addf32x2(uint64_t a, uint64_t b) {
    uint64_t d; asm("add.rn.f32x2 %0, %1, %2;" : "=l"(d) : "l"(a), "l"(b)); return d;
}

__global__ __launch_bounds__(1024, 1)
void slab_kernel(const float* __restrict__ x, float* __restrict__ out) {
    extern __shared__ char SB[];
    float* sRowPart = (float*)(SB + OFF_ROWP);   // [(band*128+lr)*33 + lane]
    float* sColPart = (float*)(SB + OFF_COLP);   // [rowgroup*512 + col], 8 rowgroups
    float* sPkM     = (float*)(SB + OFF_PKM);
    float* sPkA     = (float*)(SB + OFF_PKA);
    float* sSnapM   = (float*)(SB + OFF_SNM);    // row-indexed (lr)
    float* sSnapA   = (float*)(SB + OFF_SNA);    // col-local-indexed (127-lr)
    float* sDA      = (float*)(SB + OFF_DAE);
    float* sBandRow = (float*)(SB + OFF_BAND);   // [band*128 + lr]
    float* sCutM    = (float*)(SB + OFF_CUTM);
    float* sCutA    = (float*)(SB + OFF_CUTA);
    // last-block combine arrays alias the (dead-by-then) sRowPart region
    float* cA1  = (float*)(SB + 0);
    float* cA2  = (float*)(SB + 2048);
    float* cCT  = (float*)(SB + 4096);
    float* cRT  = (float*)(SB + 6144);
    float* cPM  = (float*)(SB + 8192);
    float* cPA  = (float*)(SB + 10240);
    float* cDAo = (float*)(SB + 12288);
    __shared__ bool amLast;

    const int blk = blockIdx.x;
    const int p = blk >> 2;
    const int s = blk & 3;
    const float* __restrict__ X = x + ((size_t)p * SZ + (size_t)s * SLAB) * SZ;

    const int tid  = threadIdx.x;
    const int w    = tid >> 5;                 // 0..31
    const int lane = tid & 31;
    const int wr = w >> 2, wc = w & 3;         // 8 rowgroups(16 rows) x 4 bands(128 cols)
    const int c0  = wc * 128;
    const int lr0 = wr * 16;
    const bool mainRole = (wc == s);
    const bool antiRole = (wc == 3 - s);

    const float4* __restrict__ base =
        reinterpret_cast<const float4*>(X + (size_t)lr0 * SZ + c0) + lane;
    const int RS4 = SZ / 4;

    uint64_t acc01 = 0ull, acc23 = 0ull;

#pragma unroll
    for (int g = 0; g < 2; ++g) {
        const int lrg = lr0 + 8 * g;

        float4 v[8];
#pragma unroll
        for (int u = 0; u < 8; u++)
            v[u] = __ldcs(base + (8 * g + u) * RS4);

        float sv[8];
#pragma unroll
        for (int u = 0; u < 8; u++) {
            uint64_t h = addf32x2(pack2(v[u].x, v[u].y), pack2(v[u].z, v[u].w));
            float lo, hi; unpack2(h, lo, hi);
            sv[u] = lo + hi;
        }

        // store per-lane row partials (conflict-free)
        {
            float* rp = sRowPart + (wc * 128 + lrg) * 33 + lane;
#pragma unroll
            for (int u = 0; u < 8; u++)
                rp[u * 33] = sv[u];
        }

        // role-warp scalars: cut pk, snapshots (acc read BEFORE that row's update) + acc update
#pragma unroll
        for (int u = 0; u < 8; u++) {
            const int lr = lrg + u;
            if (mainRole) {
                const int ls = 4 * wr + 2 * g + (u >> 2);
                const int k = u & 3;                   // compile-time
                if (lane == ls) {
                    const float pkv = (k == 0) ? v[u].x
                                    : (k == 1) ? (v[u].x + v[u].y)
                                    : (k == 2) ? ((v[u].x + v[u].y) + v[u].z)
                                    : sv[u];
                    sPkM[lr] = pkv;
                    float lo, hi, sn;
                    if (k < 2) { unpack2(acc01, lo, hi); sn = (k == 0) ? lo : hi; }
                    else       { unpack2(acc23, lo, hi); sn = (k == 2) ? lo : hi; }
                    sSnapM[lr] = sn;
                }
            }
            if (antiRole) {
                const int lsA = ((127 - lrg) >> 2) - (u >> 2);
                const int kA = 3 - (u & 3);            // compile-time
                if (lane == lsA) {
                    const float pkv = (kA == 3) ? sv[u]
                                    : (kA == 2) ? ((v[u].x + v[u].y) + v[u].z)
                                    : (kA == 1) ? (v[u].x + v[u].y)
                                    : v[u].x;
                    sPkA[lr] = pkv;
                    const float e = (kA == 0) ? v[u].x : (kA == 1) ? v[u].y
                                  : (kA == 2) ? v[u].z : v[u].w;
                    float lo, hi, sn;
                    if (kA < 2) { unpack2(acc01, lo, hi); sn = (kA == 0) ? lo : hi; }
                    else        { unpack2(acc23, lo, hi); sn = (kA == 2) ? lo : hi; }
                    sSnapA[127 - lr] = sn;
                    sDA[lr] = e;
                }
            }
            acc01 = addf32x2(acc01, pack2(v[u].x, v[u].y));
            acc23 = addf32x2(acc23, pack2(v[u].z, v[u].w));
        }
    }

    {
        float a0, a1, a2, a3;
        unpack2(acc01, a0, a1);
        unpack2(acc23, a2, a3);
        *reinterpret_cast<float4*>(sColPart + wr * SZ + c0 + lane * 4) = make_float4(a0, a1, a2, a3);
    }
    __syncthreads();

    // ---- phase 2 (split across the 1024 threads) ----
    if (tid < 512) {
        // 2a: reduce row partials from smem (no shuffles)
        const int band = tid >> 7;
        const int lr = tid & 127;
        const float* rp = sRowPart + (band * 128 + lr) * 33;
        const int lsM = lr >> 2;
        const int lsA = (127 - lr) >> 2;
        float full = 0.f, cutM = 0.f, cutA = 0.f;
#pragma unroll
        for (int k = 0; k < 32; ++k) {
            const float vv = rp[k];
            full += vv;
            if (k < lsM) cutM += vv;
            if (k < lsA) cutA += vv;
        }
        sBandRow[band * 128 + lr] = full;
        if (band == s)     sCutM[lr] = cutM + sPkM[lr];
        if (band == 3 - s) sCutA[lr] = cutA + sPkA[lr];
    } else {
        // 2b: column combine over 8 rowgroups
        const int c = tid - 512;
        float q[8];
#pragma unroll
        for (int k = 0; k < 8; ++k) q[k] = sColPart[k * SZ + c];
        float ct = 0.f;
#pragma unroll
        for (int k = 0; k < 8; ++k) ct += q[k];
        g_colsum[p][s][c] = ct;

        const int band = c >> 7;
        if (band == s) {                       // main snapshot owner: col c == global row
            const int lr = c - 128 * s;
            const int rg = lr >> 4;
            float sn = sSnapM[lr];
#pragma unroll
            for (int k = 0; k < 7; ++k) if (k < rg) sn += q[k];
            g_snapM[p][c] = sn;
        }
        if (band == 3 - s) {                   // anti snapshot owner
            const int la = c - 128 * (3 - s);  // == 127 - lr
            const int rg = (127 - la) >> 4;
            float sn = sSnapA[la];
#pragma unroll
            for (int k = 0; k < 7; ++k) if (k < rg) sn += q[k];
            g_snapA[p][c] = sn;
        }
    }
    __syncthreads();

    // ---- slab combine: rows ----
    if (tid < SLAB) {
        const int lr = tid;
        const int gr = 128 * s + lr;
        const float b0 = sBandRow[0 * 128 + lr], b1 = sBandRow[1 * 128 + lr],
                    b2 = sBandRow[2 * 128 + lr], b3 = sBandRow[3 * 128 + lr];
        g_RT[p][gr] = (b0 + b1) + (b2 + b3);

        float pm = sCutM[lr];
        if (s > 0) pm += b0;
        if (s > 1) pm += b1;
        if (s > 2) pm += b2;
        g_PM[p][gr] = pm;

        const int ab = 3 - s;
        float pa = sCutA[lr];
        if (ab > 0) pa += b0;
        if (ab > 1) pa += b1;
        if (ab > 2) pa += b2;
        g_PA[p][gr] = pa;

        g_DA[p][gr] = sDA[lr];
    }

    // ---- last-block-per-plane fused combine ----
    __threadfence();
    __syncthreads();
    if (tid == 0) {
        const unsigned t = atomicAdd(&g_cnt[p], 1u);
        amLast = (t == 3u);
        if (amLast) g_cnt[p] = 0;
    }
    __syncthreads();
    if (!amLast) return;

    if (tid < 512) {
        const int i = tid;
        const float q0 = g_colsum[p][0][i], q1 = g_colsum[p][1][i],
                    q2 = g_colsum[p][2][i], q3 = g_colsum[p][3][i];
        cCT[i] = (q0 + q1) + (q2 + q3);

        const int jm = i >> 7;
        float a1 = g_snapM[p][i];
        if (jm > 0) a1 += q0;
        if (jm > 1) a1 += q1;
        if (jm > 2) a1 += q2;
        cA1[i] = a1;

        const int ja = (SZ - 1 - i) >> 7;
        float a2 = g_snapA[p][i];
        if (ja > 0) a2 += q0;
        if (ja > 1) a2 += q1;
        if (ja > 2) a2 += q2;
        cA2[i] = a2;

        cRT[i] = g_RT[p][i]; cPM[i] = g_PM[p][i]; cPA[i] = g_PA[p][i]; cDAo[i] = g_DA[p][i];
    }
    __syncthreads();
    if (tid < 512) {
        const int i = tid;
        const int m = SZ - 1 - i;

        const float tl = cPM[i] + cA1[i];
        const float tr = cRT[i] - cPA[i] + cDAo[i] + cA2[m];
        const float bl = cPA[m] + cCT[i] - cA2[i] - cDAo[m];
        const float br = cRT[m] - cPM[m] + cCT[m] - cA1[m];

        const float inv = 1.0f / (float)(2 * i + 1);
        const int b  = p >> 3;
        const int ch = p & 7;
        float* __restrict__ o = out + ((size_t)(b * SZ + i)) * 32 + ch;
        o[0]  = tl * inv;
        o[8]  = tr * inv;
        o[16] = bl * inv;
        o[24] = br * inv;
    }
}

extern "C" void kernel_launch(void* const* d_in, const int* in_sizes, int n_in,
                              void* d_out, int out_size) {
    const float* x = (const float*)d_in[0];
    float* out = (float*)d_out;
    const int planes = in_sizes[0] / (SZ * SZ);   // 256
    static bool attrSet = false;
    if (!attrSet) {
        cudaFuncSetAttribute(slab_kernel, cudaFuncAttributeMaxDynamicSharedMemorySize, SMEM_TOTAL);
        attrSet = true;
    }
    slab_kernel<<<planes * 4, 1024, SMEM_TOTAL>>>(x, out);
}